// round 10
// baseline (speedup 1.0000x reference)
#include <cuda_runtime.h>
#include <math.h>
#include <stdint.h>

#define NE 64
#define NH 512
#define NF 2048
#define NT 2048

// ---------------- helpers ----------------
__device__ __forceinline__ uint32_t smem_u32(const void* p) {
    return (uint32_t)__cvta_generic_to_shared(p);
}
__device__ __forceinline__ uint32_t sw128(uint32_t off) { return off ^ ((off >> 3) & 0x70); }

__device__ __forceinline__ void ldm_x4(uint32_t* r, uint32_t a) {
    asm volatile("ldmatrix.sync.aligned.m8n8.x4.shared.b16 {%0,%1,%2,%3}, [%4];"
                 : "=r"(r[0]), "=r"(r[1]), "=r"(r[2]), "=r"(r[3]) : "r"(a));
}
__device__ __forceinline__ void ldm_x4_t(uint32_t* r, uint32_t a) {
    asm volatile("ldmatrix.sync.aligned.m8n8.x4.trans.shared.b16 {%0,%1,%2,%3}, [%4];"
                 : "=r"(r[0]), "=r"(r[1]), "=r"(r[2]), "=r"(r[3]) : "r"(a));
}
__device__ __forceinline__ void mma_bf16(float* c, const uint32_t* a, const uint32_t* b) {
    asm volatile(
        "mma.sync.aligned.m16n8k16.row.col.f32.bf16.bf16.f32 "
        "{%0,%1,%2,%3}, {%4,%5,%6,%7}, {%8,%9}, {%0,%1,%2,%3};"
        : "+f"(c[0]), "+f"(c[1]), "+f"(c[2]), "+f"(c[3])
        : "r"(a[0]), "r"(a[1]), "r"(a[2]), "r"(a[3]), "r"(b[0]), "r"(b[1]));
}
__device__ __forceinline__ float gelu_exact(float v) {
    return 0.5f * v * (1.0f + erff(v * 0.7071067811865476f));
}

__device__ __forceinline__ void expert_range(const int* __restrict__ counts, int e,
                                             int& base, int& cnt) {
    int b = 0, c = 0;
    #pragma unroll
    for (int j = 0; j < NE; ++j) {
        const int v = __ldg(counts + j);
        if (j < e) b += v;
        if (j == e) c = v;
    }
    base = b; cnt = c;
}

// ---------------- f32 tile load (regs) + split-convert store (smem) ----------
// Tile: 64 rows x 64 f32 cols. 256 threads: 16 threads/row (float4).
__device__ __forceinline__ void load_f32(float4* v, const float* __restrict__ src,
                                         int stride, int valid, int tid) {
    const int row0 = tid >> 4, c4 = (tid & 15) * 4;
    #pragma unroll
    for (int p = 0; p < 4; ++p) {
        const int row = p * 16 + row0;
        v[p] = (row < valid) ? *(const float4*)(src + (size_t)row * stride + c4)
                             : make_float4(0.f, 0.f, 0.f, 0.f);
    }
}
__device__ __forceinline__ void store_split(const float4* v, char* hi, char* lo, int tid) {
    const int row0 = tid >> 4, l15 = tid & 15;
    #pragma unroll
    for (int p = 0; p < 4; ++p) {
        const int row = p * 16 + row0;
        const float4 t = v[p];
        uint32_t h01, h23, l01, l23;
        asm("cvt.rn.bf16x2.f32 %0, %1, %2;" : "=r"(h01) : "f"(t.y), "f"(t.x));
        asm("cvt.rn.bf16x2.f32 %0, %1, %2;" : "=r"(h23) : "f"(t.w), "f"(t.z));
        const float rx = t.x - __uint_as_float(h01 << 16);
        const float ry = t.y - __uint_as_float(h01 & 0xffff0000u);
        const float rz = t.z - __uint_as_float(h23 << 16);
        const float rw = t.w - __uint_as_float(h23 & 0xffff0000u);
        asm("cvt.rn.bf16x2.f32 %0, %1, %2;" : "=r"(l01) : "f"(ry), "f"(rx));
        asm("cvt.rn.bf16x2.f32 %0, %1, %2;" : "=r"(l23) : "f"(rw), "f"(rz));
        const uint32_t off = sw128((uint32_t)(row * 128 + l15 * 8));
        *(uint64_t*)(hi + off) = ((uint64_t)h23 << 32) | h01;
        *(uint64_t*)(lo + off) = ((uint64_t)l23 << 32) | l01;
    }
}

// ---- w2 B half (32 k-rows x 128 f32 of n), h in {0,1} (R6-proven mapping) ----
// stored as two n64-subtiles (8KB each) within the 16KB hi region: sub = n>>6
__device__ __forceinline__ void ldgB2(float4* v, const float* __restrict__ src,
                                      int h, int tid) {
    const int row0 = tid >> 5, c4 = (tid & 31) * 4;
    #pragma unroll
    for (int p = 0; p < 4; ++p)
        v[p] = *(const float4*)(src + (size_t)(h * 32 + p * 8 + row0) * NH + c4);
}
__device__ __forceinline__ void stsB2(const float4* v, char* hi, char* lo, int h, int tid) {
    const int row0 = tid >> 5;
    const int n4 = (tid & 31) * 4;
    const int sub = n4 >> 6;
    const int nn2 = (n4 & 63) * 2;
    #pragma unroll
    for (int p = 0; p < 4; ++p) {
        const int krow = h * 32 + p * 8 + row0;
        const float4 t = v[p];
        uint32_t h01, h23, l01, l23;
        asm("cvt.rn.bf16x2.f32 %0, %1, %2;" : "=r"(h01) : "f"(t.y), "f"(t.x));
        asm("cvt.rn.bf16x2.f32 %0, %1, %2;" : "=r"(h23) : "f"(t.w), "f"(t.z));
        const float rx = t.x - __uint_as_float(h01 << 16);
        const float ry = t.y - __uint_as_float(h01 & 0xffff0000u);
        const float rz = t.z - __uint_as_float(h23 << 16);
        const float rw = t.w - __uint_as_float(h23 & 0xffff0000u);
        asm("cvt.rn.bf16x2.f32 %0, %1, %2;" : "=r"(l01) : "f"(ry), "f"(rx));
        asm("cvt.rn.bf16x2.f32 %0, %1, %2;" : "=r"(l23) : "f"(rw), "f"(rz));
        const uint32_t off = sub * 8192 + sw128((uint32_t)(krow * 128 + nn2));
        *(uint64_t*)(hi + off) = ((uint64_t)h23 << 32) | h01;
        *(uint64_t*)(lo + off) = ((uint64_t)l23 << 32) | l01;
    }
}

// smem: [stage0 32K][stage1 32K][h-hi 8K][h-lo 8K] = 80K
// stage layout phase A: [Ahi 8K][Alo 8K][Bhi 8K][Blo 8K]
// stage layout phase B: [Bhi 16K (2 subtiles)][Blo 16K (2 subtiles)]
#define BSZ (32 * 1024)
#define HOFF (2 * BSZ)
#define SMEM_TOT (HOFF + 16 * 1024)

// ---------------- zero out ----------------
__global__ void zero_out(float4* __restrict__ out) {
    out[blockIdx.x * 256 + threadIdx.x] = make_float4(0.f, 0.f, 0.f, 0.f);
}

// ---------------- fused MLP: per CTA (expert e, f-slab 64) -------------------
// Phase A: h_s = gelu(x[64,512] @ w1[f0:f0+64,:]^T) -> smem (split bf16)
// Phase B: out[64,512] += h_s @ w2[e][f0:f0+64,:]   (atomic accumulate)
__global__ void __launch_bounds__(256, 2) fused_mlp(const float* __restrict__ x,
                                                    const float* __restrict__ w1,
                                                    const float* __restrict__ w2,
                                                    float* __restrict__ out,
                                                    const int* __restrict__ counts) {
    extern __shared__ char sm[];
    const int e  = blockIdx.y;
    const int f0 = blockIdx.x * 64;
    int base, cnt;
    expert_range(counts, e, base, cnt);
    const int tid = threadIdx.x, warp = tid >> 5, lane = tid & 31;
    const int wm = warp >> 2, wn = warp & 3;
    const float* w1e = w1 + (size_t)e * NF * NH + (size_t)f0 * NH;
    const float* w2s = w2 + (size_t)e * NF * NH + (size_t)f0 * NH;

    const int arow = lane & 15, acol = lane & 16;        // A (plain)
    const int brow = (lane & 7) + ((lane >> 1) & 8);     // B gemm1 (plain, [n][k])
    const int bcol = (lane & 8) * 2;
    const int tbrow = lane & 15, tbcol = lane & 16;      // B gemm2 (trans, [k][n])
    const int r0 = lane >> 2, cp = (lane & 3) * 2;

    char* const hhi = sm + HOFF;
    char* const hlo = sm + HOFF + 8192;

    for (int mm = 0; mm < cnt; mm += 64) {
        const int rem = cnt - mm;
        const int va = rem < 64 ? rem : 64;
        const float* xa = x + (size_t)(base + mm) * NH;

        // ================= PHASE A =================
        float c[2][2][4];
        #pragma unroll
        for (int i = 0; i < 2; ++i)
            #pragma unroll
            for (int j = 0; j < 2; ++j)
                #pragma unroll
                for (int q = 0; q < 4; ++q) c[i][j][q] = 0.f;

        {   // prologue: stage k-tile 0 into buf 0
            float4 rA[4], rB[4];
            load_f32(rA, xa, NH, va, tid);
            load_f32(rB, w1e, NH, 64, tid);
            store_split(rA, sm, sm + 8192, tid);
            store_split(rB, sm + 16384, sm + 24576, tid);
        }

        for (int kt = 0; kt < 8; ++kt) {
            __syncthreads();
            char* bb = sm + (kt & 1) * BSZ;
            char* nb = sm + ((kt + 1) & 1) * BSZ;   // kt==7 -> buf0 (phase-B np0)
            float4 rA[4], rB[4];
            if (kt < 7) {
                const int k0 = (kt + 1) * 64;
                load_f32(rA, xa + k0, NH, va, tid);
                load_f32(rB, w1e + k0, NH, 64, tid);
            } else {
                ldgB2(rA, w2s, 0, tid);             // prefetch phase-B npass 0
                ldgB2(rB, w2s, 1, tid);
            }
            const uint32_t uAh = smem_u32(bb), uAl = uAh + 8192;
            const uint32_t uBh = uAh + 16384, uBl = uAh + 24576;
            #pragma unroll
            for (int kk = 0; kk < 4; ++kk) {
                uint32_t ah[2][4], al[2][4];
                #pragma unroll
                for (int mi = 0; mi < 2; ++mi) {
                    const uint32_t off =
                        sw128((uint32_t)((wm * 32 + mi * 16 + arow) * 128 + kk * 32 + acol));
                    ldm_x4(ah[mi], uAh + off);
                    ldm_x4(al[mi], uAl + off);
                }
                uint32_t bh[4], bl[4];
                {
                    const uint32_t off =
                        sw128((uint32_t)((wn * 16 + brow) * 128 + kk * 32 + bcol));
                    ldm_x4(bh, uBh + off);
                    ldm_x4(bl, uBl + off);
                }
                #pragma unroll
                for (int mi = 0; mi < 2; ++mi)
                    #pragma unroll
                    for (int j = 0; j < 2; ++j) {
                        float* cc = c[mi][j];
                        mma_bf16(cc, ah[mi], &bh[j * 2]);
                        mma_bf16(cc, ah[mi], &bl[j * 2]);
                        mma_bf16(cc, al[mi], &bh[j * 2]);
                    }
            }
            if (kt < 7) {
                store_split(rA, nb, nb + 8192, tid);
                store_split(rB, nb + 16384, nb + 24576, tid);
            } else {
                stsB2(rA, nb, nb + 16384, 0, tid);
                stsB2(rB, nb, nb + 16384, 1, tid);
            }
        }

        // phase A epilogue: gelu + split -> smem h tile (all 64 rows; pad rows are 0)
        #pragma unroll
        for (int mi = 0; mi < 2; ++mi)
            #pragma unroll
            for (int nj = 0; nj < 2; ++nj) {
                const int ncl = wn * 16 + nj * 8 + cp;
                #pragma unroll
                for (int half = 0; half < 2; ++half) {
                    const int row = wm * 32 + mi * 16 + r0 + half * 8;
                    const float g0 = gelu_exact(c[mi][nj][half * 2 + 0]);
                    const float g1 = gelu_exact(c[mi][nj][half * 2 + 1]);
                    uint32_t hp, lp;
                    asm("cvt.rn.bf16x2.f32 %0, %1, %2;" : "=r"(hp) : "f"(g1), "f"(g0));
                    const float e0 = g0 - __uint_as_float(hp << 16);
                    const float e1 = g1 - __uint_as_float(hp & 0xffff0000u);
                    asm("cvt.rn.bf16x2.f32 %0, %1, %2;" : "=r"(lp) : "f"(e1), "f"(e0));
                    const uint32_t off = sw128((uint32_t)(row * 128 + ncl * 2));
                    *(uint32_t*)(hhi + off) = hp;
                    *(uint32_t*)(hlo + off) = lp;
                }
            }
        __syncthreads();   // h visible + np0 staged in buf0

        // ================= PHASE B =================
        const uint32_t uHh = smem_u32(hhi), uHl = smem_u32(hlo);
        for (int np = 0; np < 4; ++np) {
            char* bb = sm + (np & 1) * BSZ;
            char* nb = sm + ((np + 1) & 1) * BSZ;
            float c2[2][4][4];
            #pragma unroll
            for (int i = 0; i < 2; ++i)
                #pragma unroll
                for (int j = 0; j < 4; ++j)
                    #pragma unroll
                    for (int q = 0; q < 4; ++q) c2[i][j][q] = 0.f;

            float4 rB0[4], rB1[4];
            if (np < 3) {
                ldgB2(rB0, w2s + (np + 1) * 128, 0, tid);
                ldgB2(rB1, w2s + (np + 1) * 128, 1, tid);
            }
            const uint32_t uBh = smem_u32(bb), uBl = uBh + 16384;
            #pragma unroll
            for (int kk = 0; kk < 4; ++kk) {
                uint32_t ah[2][4], al[2][4];
                #pragma unroll
                for (int mi = 0; mi < 2; ++mi) {
                    const uint32_t off =
                        sw128((uint32_t)((wm * 32 + mi * 16 + arow) * 128 + kk * 32 + acol));
                    ldm_x4(ah[mi], uHh + off);
                    ldm_x4(al[mi], uHl + off);
                }
                #pragma unroll
                for (int nbk = 0; nbk < 2; ++nbk) {
                    const int g = wn * 2 + nbk;
                    uint32_t bh[4], bl[4];
                    const uint32_t off = (uint32_t)((g >> 2) * 8192) +
                        sw128((uint32_t)((kk * 16 + tbrow) * 128 + (g & 3) * 32 + tbcol));
                    ldm_x4_t(bh, uBh + off);
                    ldm_x4_t(bl, uBl + off);
                    #pragma unroll
                    for (int mi = 0; mi < 2; ++mi)
                        #pragma unroll
                        for (int j = 0; j < 2; ++j) {
                            float* cc = c2[mi][nbk * 2 + j];
                            mma_bf16(cc, ah[mi], &bh[j * 2]);
                            mma_bf16(cc, ah[mi], &bl[j * 2]);
                            mma_bf16(cc, al[mi], &bh[j * 2]);
                        }
                }
            }
            if (np < 3) {
                stsB2(rB0, nb, nb + 16384, 0, tid);
                stsB2(rB1, nb, nb + 16384, 1, tid);
            }
            // epilogue: atomic accumulate
            #pragma unroll
            for (int mi = 0; mi < 2; ++mi)
                #pragma unroll
                for (int nj = 0; nj < 4; ++nj) {
                    const int g = wn * 2 + (nj >> 1);
                    const int rloc = wm * 32 + mi * 16 + r0;
                    const int ncol = np * 128 + g * 16 + (nj & 1) * 8 + cp;
                    if (rloc < va) {
                        float* p = &out[(size_t)(base + mm + rloc) * NH + ncol];
                        atomicAdd(p, c2[mi][nj][0]);
                        atomicAdd(p + 1, c2[mi][nj][1]);
                    }
                    if (rloc + 8 < va) {
                        float* p = &out[(size_t)(base + mm + rloc + 8) * NH + ncol];
                        atomicAdd(p, c2[mi][nj][2]);
                        atomicAdd(p + 1, c2[mi][nj][3]);
                    }
                }
            __syncthreads();
        }
    }
}

// ---------------------------------------------------------------------------
extern "C" void kernel_launch(void* const* d_in, const int* in_sizes, int n_in,
                              void* d_out, int out_size) {
    const float* x  = (const float*)d_in[0];
    const float* w1 = (const float*)d_in[1];
    const float* w2 = (const float*)d_in[2];
    const int* tokens_per_expert = (const int*)d_in[3];
    float* out = (float*)d_out;

    cudaFuncSetAttribute(fused_mlp, cudaFuncAttributeMaxDynamicSharedMemorySize, SMEM_TOT);

    zero_out<<<(NT * NH) / 1024, 256>>>((float4*)out);
    fused_mlp<<<dim3(NF / 64, NE), 256, SMEM_TOT>>>(x, w1, w2, out, tokens_per_expert);
}